// round 2
// baseline (speedup 1.0000x reference)
#include <cuda_runtime.h>
#include <cstdint>

#define EMB      128
#define NRAD     6
#define NDENSE   3
#define NT       12      // num targets
#define NTP      16      // padded targets in smem
#define MAX_ATOMS 20480
#define MAX_EDGES 660000

#define MLP_ROWS  68     // rows per MLP block
#define MLP_PAIRS 34     // row pairs per block
#define PH        35     // float2 pitch for h tile in smem (padded)

// -------- persistent device scratch (no allocations allowed) --------
__device__ float g_h[MAX_ATOMS * EMB];   // gathered atom features, L2-resident
__device__ int   g_row[MAX_ATOMS + 1];   // CSR row offsets
__device__ int   g_cnt[MAX_ATOMS];       // histogram counts
__device__ int   g_cursor[MAX_ATOMS];    // fill cursors
__device__ int   g_edges[MAX_EDGES];     // CSR edge ids
__device__ int   g_is64;                 // index dtype flag

typedef unsigned long long u64;

// -------- packed fp32x2 helpers (full-rate fp32 on Blackwell) --------
__device__ __forceinline__ u64 ffma2(u64 a, u64 b, u64 c) {
    u64 d;
    asm("fma.rn.f32x2 %0, %1, %2, %3;" : "=l"(d) : "l"(a), "l"(b), "l"(c));
    return d;
}
__device__ __forceinline__ u64 pack2(float x, float y) {
    u64 r;
    asm("mov.b64 %0, {%1, %2};" : "=l"(r) : "f"(x), "f"(y));
    return r;
}
__device__ __forceinline__ void unpack2(u64 v, float& x, float& y) {
    asm("mov.b64 {%0, %1}, %2;" : "=f"(x), "=f"(y) : "l"(v));
}
__device__ __forceinline__ float silu_f(float x) {
    return x / (1.0f + __expf(-x));
}

// ===================================================================
// Kernel 0: detect whether idnb_i is int64 or int32 (deterministic).
// ===================================================================
__global__ void detect_kernel(const void* __restrict__ idnb, int E, int n_atoms) {
    __shared__ int bad;
    if (threadIdx.x == 0) bad = 0;
    __syncthreads();
    const long long* p = (const long long*)idnb;
    int n = E / 2;
    if (n > 4096) n = 4096;
    for (int i = threadIdx.x; i < n; i += blockDim.x) {
        long long v = p[i];
        if (v < 0 || v >= (long long)n_atoms) bad = 1;
    }
    __syncthreads();
    if (threadIdx.x == 0) g_is64 = bad ? 0 : 1;
}

// ===================================================================
// Kernel 1: zero the histogram counters (20K ints only — g_h no longer
// needs zeroing: the gather kernel writes every row fully).
// ===================================================================
__global__ void zero_cnt_kernel(int n_atoms) {
    for (int i = blockIdx.x * blockDim.x + threadIdx.x; i < n_atoms;
         i += gridDim.x * blockDim.x)
        g_cnt[i] = 0;
}

// ===================================================================
// Kernel 2: histogram of destination atoms (int atomics, cheap).
// ===================================================================
__global__ void hist_kernel(const void* __restrict__ idnb, int E) {
    const bool is64 = (g_is64 != 0);
    const long long* i64 = (const long long*)idnb;
    const int* i32 = (const int*)idnb;
    for (int e = blockIdx.x * blockDim.x + threadIdx.x; e < E;
         e += gridDim.x * blockDim.x) {
        const int idx = is64 ? (int)i64[e] : i32[e];
        atomicAdd(&g_cnt[idx], 1);
    }
}

// ===================================================================
// Kernel 3: exclusive prefix sum over counts -> row offsets + cursors.
// Single block of 1024 threads, each owning a contiguous chunk.
// ===================================================================
__global__ void scan_kernel(int n_atoms, int E) {
    __shared__ int wtot[32];
    const int t = threadIdx.x;
    const int lane = t & 31, wid = t >> 5;
    const int CH = (n_atoms + 1023) >> 10;
    const int c0 = t * CH;

    int sum = 0;
    for (int i = 0; i < CH; ++i) {
        const int c = c0 + i;
        if (c < n_atoms) sum += g_cnt[c];
    }
    // inclusive warp scan of per-thread sums
    int inc = sum;
#pragma unroll
    for (int d = 1; d < 32; d <<= 1) {
        int v = __shfl_up_sync(0xffffffffu, inc, d);
        if (lane >= d) inc += v;
    }
    if (lane == 31) wtot[wid] = inc;
    __syncthreads();
    if (wid == 0) {
        int v = wtot[lane];
#pragma unroll
        for (int d = 1; d < 32; d <<= 1) {
            int u = __shfl_up_sync(0xffffffffu, v, d);
            if (lane >= d) v += u;
        }
        wtot[lane] = v;
    }
    __syncthreads();
    int run = inc - sum + (wid > 0 ? wtot[wid - 1] : 0);
    for (int i = 0; i < CH; ++i) {
        const int c = c0 + i;
        if (c < n_atoms) {
            const int v = g_cnt[c];
            g_row[c] = run;
            g_cursor[c] = run;
            run += v;
        }
    }
    if (t == 0) g_row[n_atoms] = E;
}

// ===================================================================
// Kernel 4: fill CSR edge lists.
// ===================================================================
__global__ void fill_kernel(const void* __restrict__ idnb, int E) {
    const bool is64 = (g_is64 != 0);
    const long long* i64 = (const long long*)idnb;
    const int* i32 = (const int*)idnb;
    for (int e = blockIdx.x * blockDim.x + threadIdx.x; e < E;
         e += gridDim.x * blockDim.x) {
        const int idx = is64 ? (int)i64[e] : i32[e];
        const int pos = atomicAdd(&g_cursor[idx], 1);
        g_edges[pos] = e;
    }
}

// ===================================================================
// Kernel 5: gather + gate. One warp per atom: read its edge list,
// stream 512B coalesced x rows, accumulate the gate * x sum in
// registers, write the h row ONCE (no float atomics anywhere).
// ===================================================================
__global__ void gather_kernel(const float* __restrict__ x,
                              const float* __restrict__ rbf,
                              const float* __restrict__ Wrbf,
                              int n_atoms) {
    const int lane = threadIdx.x & 31;
    const int gw = (blockIdx.x * blockDim.x + threadIdx.x) >> 5;
    const int nw = (gridDim.x * blockDim.x) >> 5;

    // W_rbf columns for this lane's 4 output cols (loop-invariant)
    float4 w[NRAD];
    const float4* w4 = (const float4*)Wrbf;
#pragma unroll
    for (int r = 0; r < NRAD; ++r) w[r] = w4[r * 32 + lane];

    const float4* x4 = (const float4*)x;

    for (int a = gw; a < n_atoms; a += nw) {
        const int s = g_row[a];
        const int epp = g_row[a + 1];
        float a0 = 0.f, a1 = 0.f, a2 = 0.f, a3 = 0.f;

        for (int base = s; base < epp; base += 32) {
            const int n = min(32, epp - base);          // >= 1
            const int eid = g_edges[base + min(lane, n - 1)];

            for (int j = 0; j < n; j += 4) {
#pragma unroll
                for (int u = 0; u < 4; ++u) {
                    const int jj = j + u;               // always < 32
                    const float m = (jj < n) ? 1.f : 0.f;
                    const int e = __shfl_sync(0xffffffffu, eid, jj);

                    const float* rb = rbf + (size_t)e * NRAD;
                    const float r0 = rb[0], r1 = rb[1], r2 = rb[2];
                    const float r3 = rb[3], r4 = rb[4], r5 = rb[5];
                    const float4 xv = x4[(size_t)e * 32 + lane];

                    float g0 = fmaf(r0, w[0].x, fmaf(r1, w[1].x, fmaf(r2, w[2].x,
                               fmaf(r3, w[3].x, fmaf(r4, w[4].x, r5 * w[5].x)))));
                    float g1 = fmaf(r0, w[0].y, fmaf(r1, w[1].y, fmaf(r2, w[2].y,
                               fmaf(r3, w[3].y, fmaf(r4, w[4].y, r5 * w[5].y)))));
                    float g2 = fmaf(r0, w[0].z, fmaf(r1, w[1].z, fmaf(r2, w[2].z,
                               fmaf(r3, w[3].z, fmaf(r4, w[4].z, r5 * w[5].z)))));
                    float g3 = fmaf(r0, w[0].w, fmaf(r1, w[1].w, fmaf(r2, w[2].w,
                               fmaf(r3, w[3].w, fmaf(r4, w[4].w, r5 * w[5].w)))));

                    a0 = fmaf(m * g0, xv.x, a0);
                    a1 = fmaf(m * g1, xv.y, a1);
                    a2 = fmaf(m * g2, xv.z, a2);
                    a3 = fmaf(m * g3, xv.w, a3);
                }
            }
        }
        ((float4*)(g_h + (size_t)a * EMB))[lane] = make_float4(a0, a1, a2, a3);
    }
}

// ===================================================================
// Kernel 6: fused MLP head (unchanged from round 1).
// ===================================================================
#define HS_BYTES   (EMB * PH * 8)          // 35840
#define WS_OFF     HS_BYTES
#define WS_BYTES   (EMB * EMB * 4)         // 65536
#define WFS_OFF    (WS_OFF + WS_BYTES)
#define WFS_BYTES  (EMB * NTP * 4)         // 8192
#define BS_OFF     (WFS_OFF + WFS_BYTES)
#define BS_BYTES   (EMB * 4)               // 512
#define SMEM_TOTAL (BS_OFF + BS_BYTES)     // 110080

__global__ __launch_bounds__(256, 2)
void mlp_kernel(const float* __restrict__ dW, const float* __restrict__ dB,
                const float* __restrict__ Wf, float* __restrict__ out,
                int n_atoms) {
    extern __shared__ char smem[];
    u64*   hsu = (u64*)smem;                       // [col][pair], pitch PH
    float* hsf = (float*)smem;                     // float view, pitch 2*PH
    float* Ws  = (float*)(smem + WS_OFF);          // layer weight [k][j]
    float* Wfs = (float*)(smem + WFS_OFF);         // final weight [k][c] padded 16
    float* bss = (float*)(smem + BS_OFF);          // bias

    const int t = threadIdx.x;
    const int rowbase = blockIdx.x * MLP_ROWS;

    // ---- load h tile (coalesced global, transpose into [col][row]) ----
    for (int idx = t; idx < MLP_ROWS * EMB; idx += 256) {
        const int r = idx >> 7, c = idx & 127;
        const int gr = rowbase + r;
        const float v = (gr < n_atoms) ? g_h[(size_t)gr * EMB + c] : 0.f;
        hsf[c * (2 * PH) + r] = v;
    }
    // ---- load final weight (padded to 16 cols) ----
    if (t < EMB) {
#pragma unroll
        for (int c = 0; c < NT; ++c) Wfs[t * NTP + c] = Wf[t * NT + c];
    }

    const int j0 = (t & 31) * 4;   // 4 output columns per thread
    const int pg = t >> 5;         // pair group 0..7

    // ---- dense layers ----
    for (int li = 0; li < NDENSE; ++li) {
        const float* W = dW + (size_t)li * EMB * EMB;
        for (int idx = t; idx < EMB * EMB; idx += 256) Ws[idx] = W[idx];
        if (t < EMB) bss[t] = dB[li * EMB + t];
        __syncthreads();

        u64 acc[5][4];
#pragma unroll
        for (int p = 0; p < 5; ++p)
#pragma unroll
            for (int q = 0; q < 4; ++q) acc[p][q] = 0ull;

#pragma unroll 4
        for (int k = 0; k < EMB; ++k) {
            const float4 wv = *(const float4*)&Ws[k * EMB + j0];
            const u64 w0 = pack2(wv.x, wv.x);
            const u64 w1 = pack2(wv.y, wv.y);
            const u64 w2 = pack2(wv.z, wv.z);
            const u64 w3 = pack2(wv.w, wv.w);
            const u64* hrow = hsu + k * PH;
#pragma unroll
            for (int p = 0; p < 4; ++p) {
                const u64 hv = hrow[pg + p * 8];
                acc[p][0] = ffma2(hv, w0, acc[p][0]);
                acc[p][1] = ffma2(hv, w1, acc[p][1]);
                acc[p][2] = ffma2(hv, w2, acc[p][2]);
                acc[p][3] = ffma2(hv, w3, acc[p][3]);
            }
            if (pg < 2) {   // tail pairs 32,33 (uniform branch per warp)
                const u64 hv = hrow[pg + 32];
                acc[4][0] = ffma2(hv, w0, acc[4][0]);
                acc[4][1] = ffma2(hv, w1, acc[4][1]);
                acc[4][2] = ffma2(hv, w2, acc[4][2]);
                acc[4][3] = ffma2(hv, w3, acc[4][3]);
            }
        }

        float b[4];
#pragma unroll
        for (int q = 0; q < 4; ++q) b[q] = bss[j0 + q];

        __syncthreads();   // all reads of hs done -> safe to overwrite

#pragma unroll
        for (int p = 0; p < 5; ++p) {
            if (p == 4 && pg >= 2) break;
            const int pr = pg + p * 8;
#pragma unroll
            for (int q = 0; q < 4; ++q) {
                float lo, hi;
                unpack2(acc[p][q], lo, hi);
                lo = silu_f(lo + b[q]);
                hi = silu_f(hi + b[q]);
                hsu[(j0 + q) * PH + pr] = pack2(lo, hi);
            }
        }
        __syncthreads();
    }

    // ---- final projection: [68,128] @ [128,12] -> out ----
    const int c = t & 15;
    const int grp = t >> 4;      // 0..15
    if (c < NT) {
#pragma unroll
        for (int i = 0; i < 3; ++i) {
            const int pr = grp + 16 * i;
            if (pr < MLP_PAIRS) {
                u64 acc = 0ull;
#pragma unroll 4
                for (int k = 0; k < EMB; ++k) {
                    const float wfv = Wfs[k * NTP + c];
                    acc = ffma2(hsu[k * PH + pr], pack2(wfv, wfv), acc);
                }
                float lo, hi;
                unpack2(acc, lo, hi);
                const int r0 = rowbase + 2 * pr;
                if (r0 < n_atoms)     out[(size_t)r0 * NT + c]       = lo;
                if (r0 + 1 < n_atoms) out[(size_t)(r0 + 1) * NT + c] = hi;
            }
        }
    }
}

// ===================================================================
extern "C" void kernel_launch(void* const* d_in, const int* in_sizes, int n_in,
                              void* d_out, int out_size) {
    const float* x    = (const float*)d_in[0];
    const float* rbf  = (const float*)d_in[1];
    const void*  idnb =               d_in[2];
    // d_in[3] = n_atoms scalar (derive from out_size instead)
    const float* Wrbf = (const float*)d_in[4];
    const float* dW   = (const float*)d_in[5];
    const float* dB   = (const float*)d_in[6];
    const float* Wf   = (const float*)d_in[7];
    float* out = (float*)d_out;

    const int E = in_sizes[0] / EMB;
    const int n_atoms = out_size / NT;

    detect_kernel<<<1, 256>>>(idnb, E, n_atoms);
    zero_cnt_kernel<<<40, 256>>>(n_atoms);
    hist_kernel<<<1184, 256>>>(idnb, E);
    scan_kernel<<<1, 1024>>>(n_atoms, E);
    fill_kernel<<<1184, 256>>>(idnb, E);
    gather_kernel<<<1184, 256>>>(x, rbf, Wrbf, n_atoms);

    cudaFuncSetAttribute(mlp_kernel, cudaFuncAttributeMaxDynamicSharedMemorySize,
                         SMEM_TOTAL);
    const int blocks = (n_atoms + MLP_ROWS - 1) / MLP_ROWS;
    mlp_kernel<<<blocks, 256, SMEM_TOTAL>>>(dW, dB, Wf, out, n_atoms);
}

// round 3
// speedup vs baseline: 1.1238x; 1.1238x over previous
#include <cuda_runtime.h>
#include <cstdint>

#define EMB      128
#define NRAD     6
#define NDENSE   3
#define NT       12      // num targets
#define NTP      16      // padded targets in smem
#define MAX_ATOMS 20480
#define MAX_EDGES 660000

#define MLP_ROWS  68     // rows per MLP block
#define MLP_PAIRS 34     // row pairs per block
#define PH        35     // float2 pitch for h tile in smem (padded)

// -------- persistent device scratch (no allocations allowed) --------
__device__ float g_h[MAX_ATOMS * EMB];   // gathered atom features, L2-resident
__device__ int   g_row[MAX_ATOMS + 1];   // CSR row offsets
__device__ int   g_cnt[MAX_ATOMS];       // histogram counts
__device__ int   g_cursor[MAX_ATOMS];    // fill cursors
__device__ int   g_edges[MAX_EDGES];     // CSR edge ids
__device__ int   g_is64;                 // index dtype flag

typedef unsigned long long u64;

// -------- packed fp32x2 helpers (full-rate fp32 on Blackwell) --------
__device__ __forceinline__ u64 ffma2(u64 a, u64 b, u64 c) {
    u64 d;
    asm("fma.rn.f32x2 %0, %1, %2, %3;" : "=l"(d) : "l"(a), "l"(b), "l"(c));
    return d;
}
__device__ __forceinline__ u64 pack2(float x, float y) {
    u64 r;
    asm("mov.b64 %0, {%1, %2};" : "=l"(r) : "f"(x), "f"(y));
    return r;
}
__device__ __forceinline__ void unpack2(u64 v, float& x, float& y) {
    asm("mov.b64 {%0, %1}, %2;" : "=f"(x), "=f"(y) : "l"(v));
}
__device__ __forceinline__ float silu_f(float x) {
    return x / (1.0f + __expf(-x));
}

// ===================================================================
// Kernel 0: detect whether idnb_i is int64 or int32 (deterministic).
// ===================================================================
__global__ void detect_kernel(const void* __restrict__ idnb, int E, int n_atoms) {
    __shared__ int bad;
    if (threadIdx.x == 0) bad = 0;
    __syncthreads();
    const long long* p = (const long long*)idnb;
    int n = E / 2;
    if (n > 4096) n = 4096;
    for (int i = threadIdx.x; i < n; i += blockDim.x) {
        long long v = p[i];
        if (v < 0 || v >= (long long)n_atoms) bad = 1;
    }
    __syncthreads();
    if (threadIdx.x == 0) g_is64 = bad ? 0 : 1;
}

// ===================================================================
// Kernel 1: zero the histogram counters.
// ===================================================================
__global__ void zero_cnt_kernel(int n_atoms) {
    for (int i = blockIdx.x * blockDim.x + threadIdx.x; i < n_atoms;
         i += gridDim.x * blockDim.x)
        g_cnt[i] = 0;
}

// ===================================================================
// Kernel 2: histogram of destination atoms (int atomics, cheap).
// ===================================================================
__global__ void hist_kernel(const void* __restrict__ idnb, int E) {
    const bool is64 = (g_is64 != 0);
    const long long* i64 = (const long long*)idnb;
    const int* i32 = (const int*)idnb;
    for (int e = blockIdx.x * blockDim.x + threadIdx.x; e < E;
         e += gridDim.x * blockDim.x) {
        const int idx = is64 ? (int)i64[e] : i32[e];
        atomicAdd(&g_cnt[idx], 1);
    }
}

// ===================================================================
// Kernel 3: exclusive prefix sum -> row offsets + cursors.
// Register-staged: all 20 chunk loads issued independently, scan done
// entirely in registers (old version serialized 20 L2-latency loads).
// ===================================================================
#define SCAN_CH 20   // covers n_atoms <= 20480 with 1024 threads
__global__ void scan_kernel(int n_atoms, int E) {
    __shared__ int wtot[32];
    const int t = threadIdx.x;
    const int lane = t & 31, wid = t >> 5;
    const int c0 = t * SCAN_CH;

    int v[SCAN_CH];
#pragma unroll
    for (int i = 0; i < SCAN_CH; ++i) {
        const int c = c0 + i;
        v[i] = (c < n_atoms) ? g_cnt[c] : 0;
    }
    int sum = 0;
#pragma unroll
    for (int i = 0; i < SCAN_CH; ++i) sum += v[i];

    // inclusive warp scan of per-thread sums
    int inc = sum;
#pragma unroll
    for (int d = 1; d < 32; d <<= 1) {
        int u = __shfl_up_sync(0xffffffffu, inc, d);
        if (lane >= d) inc += u;
    }
    if (lane == 31) wtot[wid] = inc;
    __syncthreads();
    if (wid == 0) {
        int u = wtot[lane];
#pragma unroll
        for (int d = 1; d < 32; d <<= 1) {
            int p = __shfl_up_sync(0xffffffffu, u, d);
            if (lane >= d) u += p;
        }
        wtot[lane] = u;
    }
    __syncthreads();

    int run = inc - sum + (wid > 0 ? wtot[wid - 1] : 0);
#pragma unroll
    for (int i = 0; i < SCAN_CH; ++i) {
        const int c = c0 + i;
        if (c < n_atoms) {
            g_row[c] = run;
            g_cursor[c] = run;
            run += v[i];
        }
    }
    if (t == 0) g_row[n_atoms] = E;
}

// ===================================================================
// Kernel 4: fill CSR edge lists.
// ===================================================================
__global__ void fill_kernel(const void* __restrict__ idnb, int E) {
    const bool is64 = (g_is64 != 0);
    const long long* i64 = (const long long*)idnb;
    const int* i32 = (const int*)idnb;
    for (int e = blockIdx.x * blockDim.x + threadIdx.x; e < E;
         e += gridDim.x * blockDim.x) {
        const int idx = is64 ? (int)i64[e] : i32[e];
        const int pos = atomicAdd(&g_cursor[idx], 1);
        g_edges[pos] = e;
    }
}

// ===================================================================
// Kernel 5: gather + gate. One warp per atom.
//  - each lane loads ITS OWN edge's 6 rbf values once per 32-edge
//    batch; per-edge rbf reaches all lanes via shfl (no memory).
//  - x rows loaded 8-deep (8 independent 512B LDG.128 in flight)
//    with streaming hint (read-once data, keep L2 for h/edges).
//  - h row written exactly once, no float atomics anywhere.
// ===================================================================
__global__ __launch_bounds__(256)
void gather_kernel(const float* __restrict__ x,
                   const float* __restrict__ rbf,
                   const float* __restrict__ Wrbf,
                   int n_atoms) {
    const int lane = threadIdx.x & 31;
    const int gw = (blockIdx.x * blockDim.x + threadIdx.x) >> 5;
    const int nw = (gridDim.x * blockDim.x) >> 5;
    const unsigned FULL = 0xffffffffu;

    // W_rbf columns for this lane's 4 output cols (loop-invariant)
    float4 w[NRAD];
    const float4* w4 = (const float4*)Wrbf;
#pragma unroll
    for (int r = 0; r < NRAD; ++r) w[r] = w4[r * 32 + lane];

    const float4* x4 = (const float4*)x;

    for (int a = gw; a < n_atoms; a += nw) {
        const int s  = g_row[a];
        const int e1 = g_row[a + 1];
        float a0 = 0.f, a1 = 0.f, a2 = 0.f, a3 = 0.f;

        for (int base = s; base < e1; base += 32) {
            const int n = min(32, e1 - base);            // >= 1
            const int eid = g_edges[base + min(lane, n - 1)];

            // own-edge rbf (6 scalar streaming loads per lane per batch)
            const float* rp = rbf + (size_t)eid * NRAD;
            const float rb0 = __ldcs(rp + 0), rb1 = __ldcs(rp + 1);
            const float rb2 = __ldcs(rp + 2), rb3 = __ldcs(rp + 3);
            const float rb4 = __ldcs(rp + 4), rb5 = __ldcs(rp + 5);

            for (int j = 0; j < n; j += 8) {
                int   e[8];
                float4 xv[8];
#pragma unroll
                for (int u = 0; u < 8; ++u) {
                    const int jj = min(j + u, n - 1);
                    e[u] = __shfl_sync(FULL, eid, jj);
                }
#pragma unroll
                for (int u = 0; u < 8; ++u)
                    xv[u] = __ldcs(x4 + (size_t)e[u] * 32 + lane);
#pragma unroll
                for (int u = 0; u < 8; ++u) {
                    const int jj = min(j + u, n - 1);
                    const float m = (j + u < n) ? 1.f : 0.f;
                    const float r0 = __shfl_sync(FULL, rb0, jj);
                    const float r1 = __shfl_sync(FULL, rb1, jj);
                    const float r2 = __shfl_sync(FULL, rb2, jj);
                    const float r3 = __shfl_sync(FULL, rb3, jj);
                    const float r4 = __shfl_sync(FULL, rb4, jj);
                    const float r5 = __shfl_sync(FULL, rb5, jj);

                    float g0 = fmaf(r0, w[0].x, fmaf(r1, w[1].x, fmaf(r2, w[2].x,
                               fmaf(r3, w[3].x, fmaf(r4, w[4].x, r5 * w[5].x)))));
                    float g1 = fmaf(r0, w[0].y, fmaf(r1, w[1].y, fmaf(r2, w[2].y,
                               fmaf(r3, w[3].y, fmaf(r4, w[4].y, r5 * w[5].y)))));
                    float g2 = fmaf(r0, w[0].z, fmaf(r1, w[1].z, fmaf(r2, w[2].z,
                               fmaf(r3, w[3].z, fmaf(r4, w[4].z, r5 * w[5].z)))));
                    float g3 = fmaf(r0, w[0].w, fmaf(r1, w[1].w, fmaf(r2, w[2].w,
                               fmaf(r3, w[3].w, fmaf(r4, w[4].w, r5 * w[5].w)))));

                    a0 = fmaf(m * g0, xv[u].x, a0);
                    a1 = fmaf(m * g1, xv[u].y, a1);
                    a2 = fmaf(m * g2, xv[u].z, a2);
                    a3 = fmaf(m * g3, xv[u].w, a3);
                }
            }
        }
        ((float4*)(g_h + (size_t)a * EMB))[lane] = make_float4(a0, a1, a2, a3);
    }
}

// ===================================================================
// Kernel 6: fused MLP head (unchanged — round-3 target).
// ===================================================================
#define HS_BYTES   (EMB * PH * 8)          // 35840
#define WS_OFF     HS_BYTES
#define WS_BYTES   (EMB * EMB * 4)         // 65536
#define WFS_OFF    (WS_OFF + WS_BYTES)
#define WFS_BYTES  (EMB * NTP * 4)         // 8192
#define BS_OFF     (WFS_OFF + WFS_BYTES)
#define BS_BYTES   (EMB * 4)               // 512
#define SMEM_TOTAL (BS_OFF + BS_BYTES)     // 110080

__global__ __launch_bounds__(256, 2)
void mlp_kernel(const float* __restrict__ dW, const float* __restrict__ dB,
                const float* __restrict__ Wf, float* __restrict__ out,
                int n_atoms) {
    extern __shared__ char smem[];
    u64*   hsu = (u64*)smem;                       // [col][pair], pitch PH
    float* hsf = (float*)smem;                     // float view, pitch 2*PH
    float* Ws  = (float*)(smem + WS_OFF);          // layer weight [k][j]
    float* Wfs = (float*)(smem + WFS_OFF);         // final weight [k][c] padded 16
    float* bss = (float*)(smem + BS_OFF);          // bias

    const int t = threadIdx.x;
    const int rowbase = blockIdx.x * MLP_ROWS;

    // ---- load h tile (coalesced global, transpose into [col][row]) ----
    for (int idx = t; idx < MLP_ROWS * EMB; idx += 256) {
        const int r = idx >> 7, c = idx & 127;
        const int gr = rowbase + r;
        const float v = (gr < n_atoms) ? g_h[(size_t)gr * EMB + c] : 0.f;
        hsf[c * (2 * PH) + r] = v;
    }
    // ---- load final weight (padded to 16 cols) ----
    if (t < EMB) {
#pragma unroll
        for (int c = 0; c < NT; ++c) Wfs[t * NTP + c] = Wf[t * NT + c];
    }

    const int j0 = (t & 31) * 4;   // 4 output columns per thread
    const int pg = t >> 5;         // pair group 0..7

    // ---- dense layers ----
    for (int li = 0; li < NDENSE; ++li) {
        const float* W = dW + (size_t)li * EMB * EMB;
        for (int idx = t; idx < EMB * EMB; idx += 256) Ws[idx] = W[idx];
        if (t < EMB) bss[t] = dB[li * EMB + t];
        __syncthreads();

        u64 acc[5][4];
#pragma unroll
        for (int p = 0; p < 5; ++p)
#pragma unroll
            for (int q = 0; q < 4; ++q) acc[p][q] = 0ull;

#pragma unroll 4
        for (int k = 0; k < EMB; ++k) {
            const float4 wv = *(const float4*)&Ws[k * EMB + j0];
            const u64 w0 = pack2(wv.x, wv.x);
            const u64 w1 = pack2(wv.y, wv.y);
            const u64 w2 = pack2(wv.z, wv.z);
            const u64 w3 = pack2(wv.w, wv.w);
            const u64* hrow = hsu + k * PH;
#pragma unroll
            for (int p = 0; p < 4; ++p) {
                const u64 hv = hrow[pg + p * 8];
                acc[p][0] = ffma2(hv, w0, acc[p][0]);
                acc[p][1] = ffma2(hv, w1, acc[p][1]);
                acc[p][2] = ffma2(hv, w2, acc[p][2]);
                acc[p][3] = ffma2(hv, w3, acc[p][3]);
            }
            if (pg < 2) {   // tail pairs 32,33 (uniform branch per warp)
                const u64 hv = hrow[pg + 32];
                acc[4][0] = ffma2(hv, w0, acc[4][0]);
                acc[4][1] = ffma2(hv, w1, acc[4][1]);
                acc[4][2] = ffma2(hv, w2, acc[4][2]);
                acc[4][3] = ffma2(hv, w3, acc[4][3]);
            }
        }

        float b[4];
#pragma unroll
        for (int q = 0; q < 4; ++q) b[q] = bss[j0 + q];

        __syncthreads();   // all reads of hs done -> safe to overwrite

#pragma unroll
        for (int p = 0; p < 5; ++p) {
            if (p == 4 && pg >= 2) break;
            const int pr = pg + p * 8;
#pragma unroll
            for (int q = 0; q < 4; ++q) {
                float lo, hi;
                unpack2(acc[p][q], lo, hi);
                lo = silu_f(lo + b[q]);
                hi = silu_f(hi + b[q]);
                hsu[(j0 + q) * PH + pr] = pack2(lo, hi);
            }
        }
        __syncthreads();
    }

    // ---- final projection: [68,128] @ [128,12] -> out ----
    const int c = t & 15;
    const int grp = t >> 4;      // 0..15
    if (c < NT) {
#pragma unroll
        for (int i = 0; i < 3; ++i) {
            const int pr = grp + 16 * i;
            if (pr < MLP_PAIRS) {
                u64 acc = 0ull;
#pragma unroll 4
                for (int k = 0; k < EMB; ++k) {
                    const float wfv = Wfs[k * NTP + c];
                    acc = ffma2(hsu[k * PH + pr], pack2(wfv, wfv), acc);
                }
                float lo, hi;
                unpack2(acc, lo, hi);
                const int r0 = rowbase + 2 * pr;
                if (r0 < n_atoms)     out[(size_t)r0 * NT + c]       = lo;
                if (r0 + 1 < n_atoms) out[(size_t)(r0 + 1) * NT + c] = hi;
            }
        }
    }
}

// ===================================================================
extern "C" void kernel_launch(void* const* d_in, const int* in_sizes, int n_in,
                              void* d_out, int out_size) {
    const float* x    = (const float*)d_in[0];
    const float* rbf  = (const float*)d_in[1];
    const void*  idnb =               d_in[2];
    // d_in[3] = n_atoms scalar (derive from out_size instead)
    const float* Wrbf = (const float*)d_in[4];
    const float* dW   = (const float*)d_in[5];
    const float* dB   = (const float*)d_in[6];
    const float* Wf   = (const float*)d_in[7];
    float* out = (float*)d_out;

    const int E = in_sizes[0] / EMB;
    const int n_atoms = out_size / NT;

    detect_kernel<<<1, 256>>>(idnb, E, n_atoms);
    zero_cnt_kernel<<<40, 256>>>(n_atoms);
    hist_kernel<<<1184, 256>>>(idnb, E);
    scan_kernel<<<1, 1024>>>(n_atoms, E);
    fill_kernel<<<1184, 256>>>(idnb, E);
    gather_kernel<<<1184, 256>>>(x, rbf, Wrbf, n_atoms);

    cudaFuncSetAttribute(mlp_kernel, cudaFuncAttributeMaxDynamicSharedMemorySize,
                         SMEM_TOTAL);
    const int blocks = (n_atoms + MLP_ROWS - 1) / MLP_ROWS;
    mlp_kernel<<<blocks, 256, SMEM_TOTAL>>>(dW, dB, Wf, out, n_atoms);
}